// round 14
// baseline (speedup 1.0000x reference)
#include <cuda_runtime.h>
#include <cuda_fp16.h>
#include <cstdint>
#include <math.h>

// ---------------- problem constants ----------------
#define BB 32
#define NN 4096
#define DF 768
#define DS 256
#define KSLOT 8
#define NROWS (BB*NN)        // 131072
#define SCALE_F 0.0625f      // 256^-0.5
#define EPS_ATTN 1e-8f

// ---------------- scratch (device globals; no allocations allowed) ----------------
static __device__ float g_mean[NROWS];
static __device__ float g_rstd[NROWS];
static __device__ __align__(16) __half g_Fh[(size_t)NROWS*DF];          // 201 MB
static __device__ __align__(16) __half g_k[(size_t)NROWS*DS];           // 67 MB
static __device__ __align__(16) __half g_v[(size_t)NROWS*DS];           // 67 MB
static __device__ __align__(16) __half g_WcH[512*DF];                   // fp16(Wc)
static __device__ float g_csum[512];
static __device__ float g_cbias[512];
static __device__ float g_WqT[DS*DS];
static __device__ float g_WihT[DS*768];
static __device__ float g_WhhT[DS*768];
static __device__ float g_W1T[DS*DS];
static __device__ float g_W2T[DS*DS];
static __device__ float g_q[BB*KSLOT*DS];
static __device__ float g_slots[BB*KSLOT*DS];
static __device__ float g_U[BB*KSLOT*DS];
static __device__ float g_S[BB*KSLOT];
static __device__ float g_gi[BB*KSLOT*768];
static __device__ float g_gh[BB*KSLOT*768];

// ---------------- helpers ----------------
__device__ __forceinline__ uint32_t s2u(const void* p) {
    uint32_t r;
    asm("{ .reg .u64 t; cvta.to.shared.u64 t, %1; cvt.u32.u64 %0, t; }" : "=r"(r) : "l"(p));
    return r;
}
__device__ __forceinline__ void cpa16(uint32_t dst, const void* src) {
    asm volatile("cp.async.cg.shared.global [%0], [%1], 16;" :: "r"(dst), "l"(src));
}
#define CP_COMMIT() asm volatile("cp.async.commit_group;" ::: "memory")
#define CP_WAIT0()  asm volatile("cp.async.wait_group 0;" ::: "memory")
#define CP_WAIT1()  asm volatile("cp.async.wait_group 1;" ::: "memory")

#define MMA16816(C, A, B) \
    asm volatile("mma.sync.aligned.m16n8k16.row.col.f32.f16.f16.f32 " \
        "{%0,%1,%2,%3}, {%4,%5,%6,%7}, {%8,%9}, {%0,%1,%2,%3};" \
        : "+f"((C)[0]), "+f"((C)[1]), "+f"((C)[2]), "+f"((C)[3]) \
        : "r"((A)[0]), "r"((A)[1]), "r"((A)[2]), "r"((A)[3]), "r"((B)[0]), "r"((B)[1]))

// ---------------- prep_all: Wc prep + small-weight transposes + initial slot_q ----------------
// blocks [0,512):    g-scaled Wc fp16 + colsums
// blocks [512,1280): transposes of Wih/Whh/Wq/W1/W2
// blocks [1280,1536): initial q = LN(prev)@Wq^T (raw Wq reads), slots copy, U/S zero (256 rows)
__global__ void __launch_bounds__(256) prep_all(
        const float* __restrict__ Wk, const float* __restrict__ Wv,
        const float* __restrict__ gin, const float* __restrict__ bin,
        const float* __restrict__ Wq, const float* __restrict__ Wih,
        const float* __restrict__ Whh, const float* __restrict__ W1,
        const float* __restrict__ W2, const float* __restrict__ prev,
        const float* __restrict__ gs, const float* __restrict__ bs) {
    int bid = blockIdx.x;
    int t = threadIdx.x;
    if (bid < 512) {
        int j = bid;
        const float* W = (j < 256) ? (Wk + (size_t)j*DF) : (Wv + (size_t)(j-256)*DF);
        float s = 0.f, bsum = 0.f;
        for (int f = t; f < DF; f += 256) {
            float w  = W[f];
            float wc = w * gin[f];
            g_WcH[(size_t)j*DF + f] = __float2half_rn(wc);
            s += wc; bsum += w * bin[f];
        }
        __shared__ float r1[8], r2[8];
        for (int o = 16; o; o >>= 1) { s += __shfl_down_sync(0xffffffffu, s, o); bsum += __shfl_down_sync(0xffffffffu, bsum, o); }
        if ((t & 31) == 0) { r1[t>>5] = s; r2[t>>5] = bsum; }
        __syncthreads();
        if (t == 0) {
            float ts = 0.f, tb = 0.f;
            #pragma unroll
            for (int w = 0; w < 8; w++) { ts += r1[w]; tb += r2[w]; }
            g_csum[j] = ts; g_cbias[j] = tb;
        }
    } else if (bid < 1280) {
        int i = (bid - 512) * 256 + t;      // 0 .. 196607
        int g = i / 256, d = i % 256;
        g_WihT[d*768 + g] = Wih[i];
        g_WhhT[d*768 + g] = Whh[i];
        if (i < 256*256) {
            int r = i / 256, c = i % 256;
            g_WqT[c*256 + r] = Wq[i];
            g_W1T[c*256 + r] = W1[i];
            g_W2T[c*256 + r] = W2[i];
        }
    } else {
        int row = bid - 1280;               // 0..255 (BB*KSLOT rows)
        __shared__ float sn[256];
        __shared__ float r1[8], r2[8];
        __shared__ float smv[2];
        g_U[row*256 + t] = 0.f;
        if (t == 0) g_S[row] = 0.f;
        float x = prev[row*256 + t];
        g_slots[row*256 + t] = x;
        float s = x, s2 = x*x;
        for (int o = 16; o; o >>= 1) { s += __shfl_down_sync(0xffffffffu, s, o); s2 += __shfl_down_sync(0xffffffffu, s2, o); }
        if ((t & 31) == 0) { r1[t>>5] = s; r2[t>>5] = s2; }
        __syncthreads();
        if (t == 0) {
            float ts = 0.f, ts2 = 0.f;
            #pragma unroll
            for (int w = 0; w < 8; w++) { ts += r1[w]; ts2 += r2[w]; }
            float m = ts * (1.f/256.f);
            float var = ts2 * (1.f/256.f) - m*m;
            smv[0] = m; smv[1] = rsqrtf(var + 1e-5f);
        }
        __syncthreads();
        sn[t] = (x - smv[0]) * smv[1] * gs[t] + bs[t];
        __syncthreads();
        float acc = 0.f;
        const float* wrow = Wq + (size_t)t * 256;   // q[h=t] = sum_d sn[d]*Wq[t][d]
        #pragma unroll 4
        for (int d = 0; d < 256; d++) acc += sn[d] * wrow[d];
        g_q[row*256 + t] = acc;
    }
}

// ---------------- LN stats + fp16 cast of F (one streaming pass) ----------------
__global__ void __launch_bounds__(256) row_stats_split(const float* __restrict__ F) {
    int w = threadIdx.x >> 5, l = threadIdx.x & 31;
    int row = blockIdx.x * 8 + w;
    const float4* x = (const float4*)(F + (size_t)row * DF);
    float4 a[6];
    float s = 0.f, s2 = 0.f;
    #pragma unroll
    for (int j = 0; j < 6; j++) {
        a[j] = x[l + 32*j];
        s  += a[j].x + a[j].y + a[j].z + a[j].w;
        s2 += a[j].x*a[j].x + a[j].y*a[j].y + a[j].z*a[j].z + a[j].w*a[j].w;
    }
    uint2* hdst = (uint2*)(g_Fh + (size_t)row * DF);
    #pragma unroll
    for (int j = 0; j < 6; j++) {
        float4 v = a[j];
        __half2 h0 = __floats2half2_rn(v.x, v.y);
        __half2 h1 = __floats2half2_rn(v.z, v.w);
        hdst[l + 32*j] = make_uint2(*(uint32_t*)&h0, *(uint32_t*)&h1);
    }
    for (int o = 16; o; o >>= 1) {
        s  += __shfl_down_sync(0xffffffffu, s, o);
        s2 += __shfl_down_sync(0xffffffffu, s2, o);
    }
    if (l == 0) {
        float m   = s * (1.f/768.f);
        float var = s2 * (1.f/768.f) - m*m;
        g_mean[row] = m;
        g_rstd[row] = rsqrtf(var + 1e-5f);
    }
}

// ---------------- tensor-core GEMM (fp16, BK=64, 2-stage cp.async, 2 CTA/SM) ----------------
#define GPADB 144                    // bytes per smem row: 128 data + 16 pad (9x16B, odd)
#define GTILE (128*GPADB)            // 18432
#define GSTAGE (2*GTILE)             // 36864: A, B
#define GEMM_SMEM (2*GSTAGE)         // 73728
#define NCHUNK64 (DF/64)             // 12

__global__ void __launch_bounds__(256, 2) gemm_mma(void) {
    extern __shared__ __align__(16) char smd[];
    __shared__ float s_cs[128], s_cb[128];

    const int tid = threadIdx.x;
    const int wid = tid >> 5, lane = tid & 31;
    const int wm = wid & 1, wn = wid >> 1;      // warp grid 2x4, tile 64x32
    const int bnG = blockIdx.x * 128;
    const int bm = blockIdx.y * 128;

    if (tid < 128) { s_cs[tid] = g_csum[bnG + tid]; s_cb[tid] = g_cbias[bnG + tid]; }

    const uint32_t smem_u = s2u(smd);
    const int srow = tid >> 1;           // 0..127
    const int su0  = (tid & 1) * 4;      // 16B units su0..su0+3

    auto stage = [&](int buf, int c) {
        const int kb = c * 64;
        uint32_t sb = smem_u + buf * GSTAGE;
        const __half* fa = g_Fh + (size_t)(bm + srow) * DF + kb;
        const __half* bh = g_WcH + (size_t)(bnG + srow) * DF + kb;
        uint32_t da = sb + srow * GPADB;
        uint32_t db = da + GTILE;
        #pragma unroll
        for (int j = 0; j < 4; j++) {
            int u = su0 + j;
            cpa16(da + u*16, fa + u*8);
            cpa16(db + u*16, bh + u*8);
        }
    };

    float acc[4][4][4];
    #pragma unroll
    for (int mi = 0; mi < 4; mi++)
        #pragma unroll
        for (int ni = 0; ni < 4; ni++)
            #pragma unroll
            for (int e = 0; e < 4; e++) acc[mi][ni][e] = 0.f;

    stage(0, 0); CP_COMMIT();
    stage(1, 1); CP_COMMIT();

    const int fr = lane >> 2;
    const int fk = (lane & 3) * 4;

    #pragma unroll 1
    for (int c = 0; c < NCHUNK64; c++) {
        const int buf = c & 1;
        if (c == NCHUNK64 - 1) CP_WAIT0(); else CP_WAIT1();
        __syncthreads();

        const char* Aa = smd + buf * GSTAGE;
        const char* Bb = Aa + GTILE;

        #pragma unroll
        for (int ks = 0; ks < 4; ks++) {
            uint32_t af[4][4], bfr[4][2];
            #pragma unroll
            for (int mi = 0; mi < 4; mi++) {
                uint32_t o = (wm*64 + mi*16 + fr) * GPADB + ks*32 + fk;
                af[mi][0] = *(const uint32_t*)(Aa + o);
                af[mi][1] = *(const uint32_t*)(Aa + o + 8*GPADB);
                af[mi][2] = *(const uint32_t*)(Aa + o + 16);
                af[mi][3] = *(const uint32_t*)(Aa + o + 8*GPADB + 16);
            }
            #pragma unroll
            for (int ni = 0; ni < 4; ni++) {
                uint32_t o = (wn*32 + ni*8 + fr) * GPADB + ks*32 + fk;
                bfr[ni][0] = *(const uint32_t*)(Bb + o);
                bfr[ni][1] = *(const uint32_t*)(Bb + o + 16);
            }
            #pragma unroll
            for (int mi = 0; mi < 4; mi++)
                #pragma unroll
                for (int ni = 0; ni < 4; ni++)
                    MMA16816(acc[mi][ni], af[mi], bfr[ni]);
        }

        __syncthreads();
        if (c + 2 < NCHUNK64) stage(buf, c + 2);
        CP_COMMIT();
    }

    // ---- epilogue: LN fold + fp16 store to k/v ----
    #pragma unroll
    for (int mi = 0; mi < 4; mi++) {
        int r1 = bm + wm*64 + mi*16 + fr;
        int r2 = r1 + 8;
        float rm1 = g_mean[r1], rs1 = g_rstd[r1];
        float rm2 = g_mean[r2], rs2 = g_rstd[r2];
        #pragma unroll
        for (int ni = 0; ni < 4; ni++) {
            int cl = wn*32 + ni*8 + (lane & 3)*2;
            int colg = bnG + cl;
            float cs0 = s_cs[cl], cs1 = s_cs[cl+1];
            float cb0 = s_cb[cl], cb1 = s_cb[cl+1];
            __half* base;
            int coff;
            if (colg < 256) { base = g_k; coff = colg; }
            else            { base = g_v; coff = colg - 256; }
            __half2* d1 = (__half2*)(base + (size_t)r1*DS + coff);
            __half2* d2 = (__half2*)(base + (size_t)r2*DS + coff);
            *d1 = __floats2half2_rn(
                rs1*(acc[mi][ni][0] - rm1*cs0) + cb0,
                rs1*(acc[mi][ni][1] - rm1*cs1) + cb1);
            *d2 = __floats2half2_rn(
                rs2*(acc[mi][ni][2] - rm2*cs0) + cb0,
                rs2*(acc[mi][ni][3] - rm2*cs1) + cb1);
        }
    }
}

// ---------------- fused attention sweep (fp16 k/v, ATILE 32, parallel softmax) ----------------
#define ATILE 32
#define KHPB 528                      // bytes per smem k/v row (264 halfs; 33x16B)
#define KT_B (ATILE*KHPB)             // 16896
#define KVBUF (2*KT_B)
#define CHUNKS 32
#define ATTN_SMEM_B (8192 + 2*KVBUF + 2*8*36*4 + 64)

template <bool FINAL>
__global__ void __launch_bounds__(256) attn_pass(float* __restrict__ out_attn) {
    extern __shared__ __align__(16) char asm_[];
    float* qs = (float*)asm_;                         // 8*256 fp32
    char*  kv = asm_ + 8192;                          // 2 buffers of (kt, vt) fp16
    float* Ls = (float*)(asm_ + 8192 + 2*KVBUF);      // 8*36
    float* ps = Ls + 8*36;                            // 8*36
    float* sS = ps + 8*36;                            // 8 slot sums

    int b  = blockIdx.x;
    int ch = blockIdx.y;
    int t  = threadIdx.x;

    const uint32_t kv_u = s2u(kv);
    const int lrow = t >> 3;
    const int lq   = t & 7;

    const int n0 = ch * (NN / CHUNKS);
    const char* kgb = (const char*)(g_k + ((size_t)b*NN + n0) * DS);
    const char* vgb = (const char*)(g_v + ((size_t)b*NN + n0) * DS);

    auto issue_tile = [&](int buf, int tile) {
        uint32_t kb = kv_u + buf * KVBUF;
        const char* ks = kgb + (size_t)tile * ATILE * 512 + lrow * 512 + lq * 16;
        uint32_t kd = kb + lrow * KHPB + lq * 16;
        #pragma unroll
        for (int r = 0; r < 4; r++) cpa16(kd + r*128, ks + r*128);
        if (!FINAL) {
            const char* vs = vgb + (size_t)tile * ATILE * 512 + lrow * 512 + lq * 16;
            uint32_t vd = kb + KT_B + lrow * KHPB + lq * 16;
            #pragma unroll
            for (int r = 0; r < 4; r++) cpa16(vd + r*128, vs + r*128);
        }
    };

    for (int i = t; i < 8*256; i += 256) qs[i] = g_q[b*2048 + i] * SCALE_F;
    if (t < 8) sS[t] = 0.f;

    issue_tile(0, 0); CP_COMMIT();
    issue_tile(1, 1); CP_COMMIT();

    float regU[8];
    #pragma unroll
    for (int h = 0; h < 8; h++) regU[h] = 0.f;
    float regS = 0.f;

    const int hq = t >> 5;            // logits: slot = warp id
    const int nl = t & 31;            // logits: position = lane
    const int spos = t >> 3;          // softmax: position 0..31
    const int sslot = t & 7;          // softmax: slot 0..7

    #pragma unroll 1
    for (int tile = 0; tile < (NN/CHUNKS)/ATILE; tile++) {
        const int buf = tile & 1;
        CP_WAIT1();
        __syncthreads();
        const char* ktb = kv + buf * KVBUF;
        const char* vtb = ktb + KT_B;

        // logits: thread (slot hq, position nl); 4 independent accumulators
        {
            float a4[4] = {0.f, 0.f, 0.f, 0.f};
            const float* qrow = qs + hq*256;
            const char* krow = ktb + nl * KHPB;
            #pragma unroll
            for (int d8 = 0; d8 < 32; d8++) {
                uint4 raw = *(const uint4*)(krow + d8*16);
                __half2* hp = (__half2*)&raw;
                float2 k0 = __half22float2(hp[0]), k1 = __half22float2(hp[1]);
                float2 k2 = __half22float2(hp[2]), k3 = __half22float2(hp[3]);
                float4 q0 = *(const float4*)(qrow + d8*8);
                float4 q1 = *(const float4*)(qrow + d8*8 + 4);
                a4[d8 & 3] += q0.x*k0.x + q0.y*k0.y + q0.z*k1.x + q0.w*k1.y
                            + q1.x*k2.x + q1.y*k2.y + q1.z*k3.x + q1.w*k3.y;
            }
            Ls[hq*36 + nl] = (a4[0] + a4[1]) + (a4[2] + a4[3]);
        }
        __syncthreads();

        // softmax over 8 slots, all 256 threads: (pos=t>>3, slot=t&7), width-8 shfl
        {
            float val = Ls[sslot*36 + spos];
            float m = val;
            #pragma unroll
            for (int off = 4; off; off >>= 1)
                m = fmaxf(m, __shfl_xor_sync(0xffffffffu, m, off, 8));
            float e = __expf(val - m);
            float ssum = e;
            #pragma unroll
            for (int off = 4; off; off >>= 1)
                ssum += __shfl_xor_sync(0xffffffffu, ssum, off, 8);
            float p = e / ssum;
            ps[sslot*36 + spos] = p;
            regS += p;
            if (FINAL)
                out_attn[((size_t)b*KSLOT + sslot)*NN + n0 + tile*ATILE + spos] = p;
        }
        __syncthreads();

        if (!FINAL) {
            #pragma unroll
            for (int n4 = 0; n4 < 8; n4++) {
                float4 pv[8];
                #pragma unroll
                for (int h = 0; h < 8; h++)
                    pv[h] = *(const float4*)(ps + h*36 + n4*4);
                float vv[4];
                #pragma unroll
                for (int j = 0; j < 4; j++)
                    vv[j] = __half2float(*(const __half*)(vtb + (n4*4+j)*KHPB + t*2));
                #pragma unroll
                for (int j = 0; j < 4; j++)
                    #pragma unroll
                    for (int h = 0; h < 8; h++)
                        regU[h] += ((const float*)&pv[h])[j] * vv[j];
            }
        }
        __syncthreads();
        if (tile + 2 < (NN/CHUNKS)/ATILE) issue_tile(buf, tile + 2);
        CP_COMMIT();
    }

    if (!FINAL) {
        #pragma unroll
        for (int h = 0; h < 8; h++)
            atomicAdd(&g_U[((size_t)b*KSLOT + h)*DS + t], regU[h]);
    }
    atomicAdd(&sS[sslot], regS);
    __syncthreads();
    if (t < 8) atomicAdd(&g_S[b*KSLOT + t], sS[t]);
}

// ---------------- GRU gate GEMMs ----------------
__global__ void __launch_bounds__(256) gru_gemm(const float* __restrict__ bih, const float* __restrict__ bhh) {
    int blk = blockIdx.x;
    int b = blk / 24, gc = blk % 24;
    __shared__ float su[8*256], ss[8*256];
    int t = threadIdx.x;
    for (int i = t; i < 2048; i += 256) {
        int k = i >> 8;
        su[i] = g_U[b*2048 + i] / (g_S[b*8 + k] + EPS_ATTN);
        ss[i] = g_slots[b*2048 + i];
    }
    __syncthreads();
    int g = gc*32 + (t & 31);
    int k = t >> 5;
    float gia = bih[g], gha = bhh[g];
    float gib = 0.f, ghb = 0.f;
    const float* su_k = su + k*256;
    const float* ss_k = ss + k*256;
    #pragma unroll 8
    for (int d = 0; d < 256; d += 2) {
        gia += su_k[d]   * g_WihT[d*768 + g];
        gib += su_k[d+1] * g_WihT[(d+1)*768 + g];
        gha += ss_k[d]   * g_WhhT[d*768 + g];
        ghb += ss_k[d+1] * g_WhhT[(d+1)*768 + g];
    }
    g_gi[((size_t)b*8 + k)*768 + g] = gia + gib;
    g_gh[((size_t)b*8 + k)*768 + g] = gha + ghb;
}

// ---------------- GRU combine + LN + MLP + next-iteration q (fused slot_q tail) ----------------
__global__ void __launch_bounds__(256) gru_mlp(const float* __restrict__ gm, const float* __restrict__ bm,
                                               const float* __restrict__ b1, const float* __restrict__ b2,
                                               const float* __restrict__ gs, const float* __restrict__ bs) {
    int bk = blockIdx.x;
    int t = threadIdx.x;
    const float* gi = g_gi + (size_t)bk*768;
    const float* gh = g_gh + (size_t)bk*768;
    float sl = g_slots[bk*256 + t];
    float r  = 1.f / (1.f + __expf(-(gi[t]       + gh[t])));
    float z  = 1.f / (1.f + __expf(-(gi[256 + t] + gh[256 + t])));
    float nn = tanhf(gi[512 + t] + r * gh[512 + t]);
    float h  = (1.f - z) * nn + z * sl;

    __shared__ float hn[256], ms[256];
    __shared__ float r1[8], r2[8];
    __shared__ float smv[2];
    float s = h, s2 = h*h;
    for (int o = 16; o; o >>= 1) { s += __shfl_down_sync(0xffffffffu, s, o); s2 += __shfl_down_sync(0xffffffffu, s2, o); }
    if ((t & 31) == 0) { r1[t>>5] = s; r2[t>>5] = s2; }
    __syncthreads();
    if (t == 0) {
        float ts = 0.f, ts2 = 0.f;
        #pragma unroll
        for (int w = 0; w < 8; w++) { ts += r1[w]; ts2 += r2[w]; }
        float m = ts * (1.f/256.f);
        float var = ts2 * (1.f/256.f) - m*m;
        smv[0] = m; smv[1] = rsqrtf(var + 1e-5f);
    }
    __syncthreads();
    hn[t] = (h - smv[0]) * smv[1] * gm[t] + bm[t];
    __syncthreads();
    float acc = b1[t];
    #pragma unroll 4
    for (int d = 0; d < 256; d++) acc += hn[d] * g_W1T[d*256 + t];
    ms[t] = fmaxf(acc, 0.f);
    __syncthreads();
    float o = h + b2[t];
    #pragma unroll 4
    for (int j = 0; j < 256; j++) o += ms[j] * g_W2T[j*256 + t];
    g_slots[bk*256 + t] = o;

    // ---- fused slot_q tail: zero U/S, q = LN(new slots) @ Wq^T ----
    g_U[bk*256 + t] = 0.f;
    if (t == 0) g_S[bk] = 0.f;
    __syncthreads();
    s = o; s2 = o*o;
    for (int off = 16; off; off >>= 1) { s += __shfl_down_sync(0xffffffffu, s, off); s2 += __shfl_down_sync(0xffffffffu, s2, off); }
    if ((t & 31) == 0) { r1[t>>5] = s; r2[t>>5] = s2; }
    __syncthreads();
    if (t == 0) {
        float ts = 0.f, ts2 = 0.f;
        #pragma unroll
        for (int w = 0; w < 8; w++) { ts += r1[w]; ts2 += r2[w]; }
        float m = ts * (1.f/256.f);
        float var = ts2 * (1.f/256.f) - m*m;
        smv[0] = m; smv[1] = rsqrtf(var + 1e-5f);
    }
    __syncthreads();
    hn[t] = (o - smv[0]) * smv[1] * gs[t] + bs[t];
    __syncthreads();
    float qa = 0.f;
    #pragma unroll 4
    for (int d = 0; d < 256; d++) qa += hn[d] * g_WqT[d*256 + t];
    g_q[bk*256 + t] = qa;
}

// ---------------- final confidence blend ----------------
__global__ void __launch_bounds__(256) finalize(const float* __restrict__ prev, float* __restrict__ out_slots) {
    int bk = blockIdx.x;
    int t = threadIdx.x;
    float mean = g_S[bk] * (1.f / 4096.f);
    float mask = 1.f / (1.f + __expf(-mean));
    out_slots[bk*256 + t] = g_slots[bk*256 + t] * mask + prev[bk*256 + t] * (1.f - mask);
}

// ---------------- launch ----------------
extern "C" void kernel_launch(void* const* d_in, const int* in_sizes, int n_in,
                              void* d_out, int out_size) {
    const float* features = (const float*)d_in[0];
    const float* prev     = (const float*)d_in[1];
    const float* gin      = (const float*)d_in[2];
    const float* bin      = (const float*)d_in[3];
    const float* gs       = (const float*)d_in[4];
    const float* bs       = (const float*)d_in[5];
    const float* gm       = (const float*)d_in[6];
    const float* bm       = (const float*)d_in[7];
    const float* Wq       = (const float*)d_in[8];
    const float* Wk       = (const float*)d_in[9];
    const float* Wv       = (const float*)d_in[10];
    const float* Wih      = (const float*)d_in[11];
    const float* Whh      = (const float*)d_in[12];
    const float* bih      = (const float*)d_in[13];
    const float* bhh      = (const float*)d_in[14];
    const float* W1       = (const float*)d_in[15];
    const float* b1       = (const float*)d_in[16];
    const float* W2       = (const float*)d_in[17];
    const float* b2       = (const float*)d_in[18];

    float* out_slots = (float*)d_out;
    float* out_attn  = out_slots + BB*KSLOT*DS;

    cudaFuncSetAttribute((const void*)attn_pass<false>, cudaFuncAttributeMaxDynamicSharedMemorySize, ATTN_SMEM_B);
    cudaFuncSetAttribute((const void*)attn_pass<true>,  cudaFuncAttributeMaxDynamicSharedMemorySize, ATTN_SMEM_B);
    cudaFuncSetAttribute((const void*)gemm_mma, cudaFuncAttributeMaxDynamicSharedMemorySize, GEMM_SMEM);

    // launch 1: all prep (Wc fp16 + colsums, transposes, initial q/slots/U/S: 512+768+256 blocks)
    prep_all<<<1536, 256>>>(Wk, Wv, gin, bin, Wq, Wih, Whh, W1, W2, prev, gs, bs);
    // launch 2: LN stats + fp16 cast
    row_stats_split<<<NROWS/8, 256>>>(features);
    // launch 3: projection GEMM
    gemm_mma<<<dim3(4, NROWS/128), 256, GEMM_SMEM>>>();

    // launch 4 (PROFILED): first attention sweep
    for (int it = 0; it < 3; it++) {
        attn_pass<false><<<dim3(BB, CHUNKS), 256, ATTN_SMEM_B>>>(nullptr);
        gru_gemm<<<BB*24, 256>>>(bih, bhh);
        gru_mlp<<<BB*KSLOT, 256>>>(gm, bm, b1, b2, gs, bs);
    }

    attn_pass<true><<<dim3(BB, CHUNKS), 256, ATTN_SMEM_B>>>(out_attn);
    finalize<<<BB*KSLOT, 256>>>(prev, out_slots);

    (void)in_sizes; (void)n_in; (void)out_size;
}

// round 15
// speedup vs baseline: 1.1008x; 1.1008x over previous
#include <cuda_runtime.h>
#include <cuda_fp16.h>
#include <cstdint>
#include <math.h>

// ---------------- problem constants ----------------
#define BB 32
#define NN 4096
#define DF 768
#define DS 256
#define KSLOT 8
#define NROWS (BB*NN)        // 131072
#define SCALE_F 0.0625f      // 256^-0.5
#define EPS_ATTN 1e-8f

// ---------------- scratch (device globals; no allocations allowed) ----------------
static __device__ float g_mean[NROWS];
static __device__ float g_rstd[NROWS];
static __device__ __align__(16) __half g_Fh[(size_t)NROWS*DF];          // 201 MB
static __device__ __align__(16) __half g_k[(size_t)NROWS*DS];           // 67 MB
static __device__ __align__(16) __half g_v[(size_t)NROWS*DS];           // 67 MB
static __device__ __align__(16) __half g_WcH[512*DF];                   // fp16(Wc)
static __device__ float g_csum[512];
static __device__ float g_cbias[512];
static __device__ float g_WqT[DS*DS];
static __device__ float g_WihT[DS*768];
static __device__ float g_WhhT[DS*768];
static __device__ float g_W1T[DS*DS];
static __device__ float g_W2T[DS*DS];
static __device__ float g_q[BB*KSLOT*DS];
static __device__ float g_slots[BB*KSLOT*DS];
static __device__ float g_U[BB*KSLOT*DS];
static __device__ float g_S[BB*KSLOT];
static __device__ float g_gi[BB*KSLOT*768];
static __device__ float g_gh[BB*KSLOT*768];

// ---------------- helpers ----------------
__device__ __forceinline__ uint32_t s2u(const void* p) {
    uint32_t r;
    asm("{ .reg .u64 t; cvta.to.shared.u64 t, %1; cvt.u32.u64 %0, t; }" : "=r"(r) : "l"(p));
    return r;
}
__device__ __forceinline__ void cpa16(uint32_t dst, const void* src) {
    asm volatile("cp.async.cg.shared.global [%0], [%1], 16;" :: "r"(dst), "l"(src));
}
#define CP_COMMIT() asm volatile("cp.async.commit_group;" ::: "memory")
#define CP_WAIT0()  asm volatile("cp.async.wait_group 0;" ::: "memory")
#define CP_WAIT3()  asm volatile("cp.async.wait_group 3;" ::: "memory")

#define MMA16816(C, A, B) \
    asm volatile("mma.sync.aligned.m16n8k16.row.col.f32.f16.f16.f32 " \
        "{%0,%1,%2,%3}, {%4,%5,%6,%7}, {%8,%9}, {%0,%1,%2,%3};" \
        : "+f"((C)[0]), "+f"((C)[1]), "+f"((C)[2]), "+f"((C)[3]) \
        : "r"((A)[0]), "r"((A)[1]), "r"((A)[2]), "r"((A)[3]), "r"((B)[0]), "r"((B)[1]))

// ---------------- prep_all: Wc prep + small-weight transposes + initial slot_q ----------------
__global__ void __launch_bounds__(256) prep_all(
        const float* __restrict__ Wk, const float* __restrict__ Wv,
        const float* __restrict__ gin, const float* __restrict__ bin,
        const float* __restrict__ Wq, const float* __restrict__ Wih,
        const float* __restrict__ Whh, const float* __restrict__ W1,
        const float* __restrict__ W2, const float* __restrict__ prev,
        const float* __restrict__ gs, const float* __restrict__ bs) {
    int bid = blockIdx.x;
    int t = threadIdx.x;
    if (bid < 512) {
        int j = bid;
        const float* W = (j < 256) ? (Wk + (size_t)j*DF) : (Wv + (size_t)(j-256)*DF);
        float s = 0.f, bsum = 0.f;
        for (int f = t; f < DF; f += 256) {
            float w  = W[f];
            float wc = w * gin[f];
            g_WcH[(size_t)j*DF + f] = __float2half_rn(wc);
            s += wc; bsum += w * bin[f];
        }
        __shared__ float r1[8], r2[8];
        for (int o = 16; o; o >>= 1) { s += __shfl_down_sync(0xffffffffu, s, o); bsum += __shfl_down_sync(0xffffffffu, bsum, o); }
        if ((t & 31) == 0) { r1[t>>5] = s; r2[t>>5] = bsum; }
        __syncthreads();
        if (t == 0) {
            float ts = 0.f, tb = 0.f;
            #pragma unroll
            for (int w = 0; w < 8; w++) { ts += r1[w]; tb += r2[w]; }
            g_csum[j] = ts; g_cbias[j] = tb;
        }
    } else if (bid < 1280) {
        int i = (bid - 512) * 256 + t;      // 0 .. 196607
        int g = i / 256, d = i % 256;
        g_WihT[d*768 + g] = Wih[i];
        g_WhhT[d*768 + g] = Whh[i];
        if (i < 256*256) {
            int r = i / 256, c = i % 256;
            g_WqT[c*256 + r] = Wq[i];
            g_W1T[c*256 + r] = W1[i];
            g_W2T[c*256 + r] = W2[i];
        }
    } else {
        int row = bid - 1280;               // 0..255 (BB*KSLOT rows)
        __shared__ float sn[256];
        __shared__ float r1[8], r2[8];
        __shared__ float smv[2];
        g_U[row*256 + t] = 0.f;
        if (t == 0) g_S[row] = 0.f;
        float x = prev[row*256 + t];
        g_slots[row*256 + t] = x;
        float s = x, s2 = x*x;
        for (int o = 16; o; o >>= 1) { s += __shfl_down_sync(0xffffffffu, s, o); s2 += __shfl_down_sync(0xffffffffu, s2, o); }
        if ((t & 31) == 0) { r1[t>>5] = s; r2[t>>5] = s2; }
        __syncthreads();
        if (t == 0) {
            float ts = 0.f, ts2 = 0.f;
            #pragma unroll
            for (int w = 0; w < 8; w++) { ts += r1[w]; ts2 += r2[w]; }
            float m = ts * (1.f/256.f);
            float var = ts2 * (1.f/256.f) - m*m;
            smv[0] = m; smv[1] = rsqrtf(var + 1e-5f);
        }
        __syncthreads();
        sn[t] = (x - smv[0]) * smv[1] * gs[t] + bs[t];
        __syncthreads();
        float acc = 0.f;
        const float* wrow = Wq + (size_t)t * 256;
        #pragma unroll 4
        for (int d = 0; d < 256; d++) acc += sn[d] * wrow[d];
        g_q[row*256 + t] = acc;
    }
}

// ---------------- LN stats + fp16 cast of F (one streaming pass) ----------------
__global__ void __launch_bounds__(256) row_stats_split(const float* __restrict__ F) {
    int w = threadIdx.x >> 5, l = threadIdx.x & 31;
    int row = blockIdx.x * 8 + w;
    const float4* x = (const float4*)(F + (size_t)row * DF);
    float4 a[6];
    float s = 0.f, s2 = 0.f;
    #pragma unroll
    for (int j = 0; j < 6; j++) {
        a[j] = x[l + 32*j];
        s  += a[j].x + a[j].y + a[j].z + a[j].w;
        s2 += a[j].x*a[j].x + a[j].y*a[j].y + a[j].z*a[j].z + a[j].w*a[j].w;
    }
    uint2* hdst = (uint2*)(g_Fh + (size_t)row * DF);
    #pragma unroll
    for (int j = 0; j < 6; j++) {
        float4 v = a[j];
        __half2 h0 = __floats2half2_rn(v.x, v.y);
        __half2 h1 = __floats2half2_rn(v.z, v.w);
        hdst[l + 32*j] = make_uint2(*(uint32_t*)&h0, *(uint32_t*)&h1);
    }
    for (int o = 16; o; o >>= 1) {
        s  += __shfl_down_sync(0xffffffffu, s, o);
        s2 += __shfl_down_sync(0xffffffffu, s2, o);
    }
    if (l == 0) {
        float m   = s * (1.f/768.f);
        float var = s2 * (1.f/768.f) - m*m;
        g_mean[row] = m;
        g_rstd[row] = rsqrtf(var + 1e-5f);
    }
}

// ---------------- tensor-core GEMM (R10 config: fp16, BK=32, 4-stage cp.async, 2 CTA/SM) ----------------
#define GPADB 80
#define GTILE (128*GPADB)
#define GSTAGE (2*GTILE)
#define GNSTAGE 4
#define GEMM_SMEM (GNSTAGE*GSTAGE)   // 81920
#define NCHUNK (DF/32)               // 24

__global__ void __launch_bounds__(256, 2) gemm_mma(void) {
    extern __shared__ __align__(16) char smd[];
    __shared__ float s_cs[128], s_cb[128];

    const int tid = threadIdx.x;
    const int wid = tid >> 5, lane = tid & 31;
    const int wm = wid & 1, wn = wid >> 1;
    const int bnG = blockIdx.x * 128;
    const int bm = blockIdx.y * 128;

    if (tid < 128) { s_cs[tid] = g_csum[bnG + tid]; s_cb[tid] = g_cbias[bnG + tid]; }

    const uint32_t smem_u = s2u(smd);
    const int arow = tid >> 2;
    const int aq   = tid & 3;

    auto stage = [&](int buf, int c) {
        const int kb = c * 32;
        uint32_t sb = smem_u + buf * GSTAGE;
        const __half* fa = g_Fh + (size_t)(bm + arow) * DF + kb + aq * 8;
        uint32_t da = sb + arow * GPADB + aq * 16;
        cpa16(da,            fa);
        cpa16(da + 64*GPADB, fa + (size_t)64*DF);
        const __half* bh = g_WcH + (size_t)(bnG + arow) * DF + kb + aq * 8;
        uint32_t db = sb + GTILE + arow * GPADB + aq * 16;
        cpa16(db,            bh);
        cpa16(db + 64*GPADB, bh + (size_t)64*DF);
    };

    float acc[4][4][4];
    #pragma unroll
    for (int mi = 0; mi < 4; mi++)
        #pragma unroll
        for (int ni = 0; ni < 4; ni++)
            #pragma unroll
            for (int e = 0; e < 4; e++) acc[mi][ni][e] = 0.f;

    stage(0, 0); CP_COMMIT();
    stage(1, 1); CP_COMMIT();
    stage(2, 2); CP_COMMIT();
    stage(3, 3); CP_COMMIT();

    const int fr = lane >> 2;
    const int fk = (lane & 3) * 4;

    #pragma unroll 1
    for (int c = 0; c < NCHUNK; c++) {
        const int buf = c & 3;
        CP_WAIT3();
        __syncthreads();

        const char* Aa = smd + buf * GSTAGE;
        const char* Bb = Aa + GTILE;

        #pragma unroll
        for (int ks = 0; ks < 2; ks++) {
            uint32_t af[4][4], bfr[4][2];
            #pragma unroll
            for (int mi = 0; mi < 4; mi++) {
                uint32_t o = (wm*64 + mi*16 + fr) * GPADB + ks*32 + fk;
                af[mi][0] = *(const uint32_t*)(Aa + o);
                af[mi][1] = *(const uint32_t*)(Aa + o + 8*GPADB);
                af[mi][2] = *(const uint32_t*)(Aa + o + 16);
                af[mi][3] = *(const uint32_t*)(Aa + o + 8*GPADB + 16);
            }
            #pragma unroll
            for (int ni = 0; ni < 4; ni++) {
                uint32_t o = (wn*32 + ni*8 + fr) * GPADB + ks*32 + fk;
                bfr[ni][0] = *(const uint32_t*)(Bb + o);
                bfr[ni][1] = *(const uint32_t*)(Bb + o + 16);
            }
            #pragma unroll
            for (int mi = 0; mi < 4; mi++)
                #pragma unroll
                for (int ni = 0; ni < 4; ni++)
                    MMA16816(acc[mi][ni], af[mi], bfr[ni]);
        }

        __syncthreads();
        if (c + GNSTAGE < NCHUNK) stage(buf, c + GNSTAGE);
        CP_COMMIT();
    }

    // ---- epilogue: LN fold + fp16 store to k/v ----
    #pragma unroll
    for (int mi = 0; mi < 4; mi++) {
        int r1 = bm + wm*64 + mi*16 + fr;
        int r2 = r1 + 8;
        float rm1 = g_mean[r1], rs1 = g_rstd[r1];
        float rm2 = g_mean[r2], rs2 = g_rstd[r2];
        #pragma unroll
        for (int ni = 0; ni < 4; ni++) {
            int cl = wn*32 + ni*8 + (lane & 3)*2;
            int colg = bnG + cl;
            float cs0 = s_cs[cl], cs1 = s_cs[cl+1];
            float cb0 = s_cb[cl], cb1 = s_cb[cl+1];
            __half* base;
            int coff;
            if (colg < 256) { base = g_k; coff = colg; }
            else            { base = g_v; coff = colg - 256; }
            __half2* d1 = (__half2*)(base + (size_t)r1*DS + coff);
            __half2* d2 = (__half2*)(base + (size_t)r2*DS + coff);
            *d1 = __floats2half2_rn(
                rs1*(acc[mi][ni][0] - rm1*cs0) + cb0,
                rs1*(acc[mi][ni][1] - rm1*cs1) + cb1);
            *d2 = __floats2half2_rn(
                rs2*(acc[mi][ni][2] - rm2*cs0) + cb0,
                rs2*(acc[mi][ni][3] - rm2*cs1) + cb1);
        }
    }
}

// ---------------- fused attention sweep (fp16 k/v, single buffer -> 5 CTA/SM) ----------------
#define ATILE 32
#define KHPB 528                      // bytes per smem k/v row (264 halfs; 33x16B)
#define KT_B (ATILE*KHPB)             // 16896
#define KVBUF (2*KT_B)                // 33792 (k + v, single buffer)
#define CHUNKS 32
#define ATTN_SMEM_B (8192 + KVBUF + 2*8*36*4 + 64)   // 44352 -> 5 CTAs/SM

template <bool FINAL>
__global__ void __launch_bounds__(256) attn_pass(float* __restrict__ out_attn) {
    extern __shared__ __align__(16) char asm_[];
    float* qs = (float*)asm_;                         // 8*256 fp32
    char*  kv = asm_ + 8192;                          // single (kt, vt) fp16 buffer
    float* Ls = (float*)(asm_ + 8192 + KVBUF);        // 8*36
    float* ps = Ls + 8*36;                            // 8*36
    float* sS = ps + 8*36;                            // 8 slot sums

    int b  = blockIdx.x;
    int ch = blockIdx.y;
    int t  = threadIdx.x;

    const uint32_t kv_u = s2u(kv);
    const int lrow = t >> 3;
    const int lq   = t & 7;

    const int n0 = ch * (NN / CHUNKS);
    const char* kgb = (const char*)(g_k + ((size_t)b*NN + n0) * DS);
    const char* vgb = (const char*)(g_v + ((size_t)b*NN + n0) * DS);

    auto issue_tile = [&](int tile) {
        const char* ks = kgb + (size_t)tile * ATILE * 512 + lrow * 512 + lq * 16;
        uint32_t kd = kv_u + lrow * KHPB + lq * 16;
        #pragma unroll
        for (int r = 0; r < 4; r++) cpa16(kd + r*128, ks + r*128);
        if (!FINAL) {
            const char* vs = vgb + (size_t)tile * ATILE * 512 + lrow * 512 + lq * 16;
            uint32_t vd = kv_u + KT_B + lrow * KHPB + lq * 16;
            #pragma unroll
            for (int r = 0; r < 4; r++) cpa16(vd + r*128, vs + r*128);
        }
        CP_COMMIT();
    };

    issue_tile(0);
    for (int i = t; i < 8*256; i += 256) qs[i] = g_q[b*2048 + i] * SCALE_F;
    if (t < 8) sS[t] = 0.f;

    float regU[8];
    #pragma unroll
    for (int h = 0; h < 8; h++) regU[h] = 0.f;
    float regS = 0.f;

    const int hq = t >> 5;            // logits: slot = warp id
    const int nl = t & 31;            // logits: position = lane
    const int spos = t >> 3;          // softmax: position 0..31
    const int sslot = t & 7;          // softmax: slot 0..7

    #pragma unroll 1
    for (int tile = 0; tile < (NN/CHUNKS)/ATILE; tile++) {
        CP_WAIT0();
        __syncthreads();
        const char* ktb = kv;
        const char* vtb = kv + KT_B;

        // logits: thread (slot hq, position nl); 4 independent accumulators
        {
            float a4[4] = {0.f, 0.f, 0.f, 0.f};
            const float* qrow = qs + hq*256;
            const char* krow = ktb + nl * KHPB;
            #pragma unroll
            for (int d8 = 0; d8 < 32; d8++) {
                uint4 raw = *(const uint4*)(krow + d8*16);
                __half2* hp = (__half2*)&raw;
                float2 k0 = __half22float2(hp[0]), k1 = __half22float2(hp[1]);
                float2 k2 = __half22float2(hp[2]), k3 = __half22float2(hp[3]);
                float4 q0 = *(const float4*)(qrow + d8*8);
                float4 q1 = *(const float4*)(qrow + d8*8 + 4);
                a4[d8 & 3] += q0.x*k0.x + q0.y*k0.y + q0.z*k1.x + q0.w*k1.y
                            + q1.x*k2.x + q1.y*k2.y + q1.z*k3.x + q1.w*k3.y;
            }
            Ls[hq*36 + nl] = (a4[0] + a4[1]) + (a4[2] + a4[3]);
        }
        __syncthreads();

        // softmax over 8 slots, all 256 threads: (pos=t>>3, slot=t&7), width-8 shfl
        {
            float val = Ls[sslot*36 + spos];
            float m = val;
            #pragma unroll
            for (int off = 4; off; off >>= 1)
                m = fmaxf(m, __shfl_xor_sync(0xffffffffu, m, off, 8));
            float e = __expf(val - m);
            float ssum = e;
            #pragma unroll
            for (int off = 4; off; off >>= 1)
                ssum += __shfl_xor_sync(0xffffffffu, ssum, off, 8);
            float p = e / ssum;
            ps[sslot*36 + spos] = p;
            regS += p;
            if (FINAL)
                out_attn[((size_t)b*KSLOT + sslot)*NN + n0 + tile*ATILE + spos] = p;
        }
        __syncthreads();

        if (!FINAL) {
            #pragma unroll
            for (int n4 = 0; n4 < 8; n4++) {
                float4 pv[8];
                #pragma unroll
                for (int h = 0; h < 8; h++)
                    pv[h] = *(const float4*)(ps + h*36 + n4*4);
                float vv[4];
                #pragma unroll
                for (int j = 0; j < 4; j++)
                    vv[j] = __half2float(*(const __half*)(vtb + (n4*4+j)*KHPB + t*2));
                #pragma unroll
                for (int j = 0; j < 4; j++)
                    #pragma unroll
                    for (int h = 0; h < 8; h++)
                        regU[h] += ((const float*)&pv[h])[j] * vv[j];
            }
        }
        __syncthreads();
        if (tile + 1 < (NN/CHUNKS)/ATILE) issue_tile(tile + 1);
    }

    if (!FINAL) {
        #pragma unroll
        for (int h = 0; h < 8; h++)
            atomicAdd(&g_U[((size_t)b*KSLOT + h)*DS + t], regU[h]);
    }
    atomicAdd(&sS[sslot], regS);
    __syncthreads();
    if (t < 8) atomicAdd(&g_S[b*KSLOT + t], sS[t]);
}

// ---------------- GRU gate GEMMs ----------------
__global__ void __launch_bounds__(256) gru_gemm(const float* __restrict__ bih, const float* __restrict__ bhh) {
    int blk = blockIdx.x;
    int b = blk / 24, gc = blk % 24;
    __shared__ float su[8*256], ss[8*256];
    int t = threadIdx.x;
    for (int i = t; i < 2048; i += 256) {
        int k = i >> 8;
        su[i] = g_U[b*2048 + i] / (g_S[b*8 + k] + EPS_ATTN);
        ss[i] = g_slots[b*2048 + i];
    }
    __syncthreads();
    int g = gc*32 + (t & 31);
    int k = t >> 5;
    float gia = bih[g], gha = bhh[g];
    float gib = 0.f, ghb = 0.f;
    const float* su_k = su + k*256;
    const float* ss_k = ss + k*256;
    #pragma unroll 8
    for (int d = 0; d < 256; d += 2) {
        gia += su_k[d]   * g_WihT[d*768 + g];
        gib += su_k[d+1] * g_WihT[(d+1)*768 + g];
        gha += ss_k[d]   * g_WhhT[d*768 + g];
        ghb += ss_k[d+1] * g_WhhT[(d+1)*768 + g];
    }
    g_gi[((size_t)b*8 + k)*768 + g] = gia + gib;
    g_gh[((size_t)b*8 + k)*768 + g] = gha + ghb;
}

// ---------------- GRU combine + LN + MLP + next-iteration q (fused slot_q tail) ----------------
__global__ void __launch_bounds__(256) gru_mlp(const float* __restrict__ gm, const float* __restrict__ bm,
                                               const float* __restrict__ b1, const float* __restrict__ b2,
                                               const float* __restrict__ gs, const float* __restrict__ bs) {
    int bk = blockIdx.x;
    int t = threadIdx.x;
    const float* gi = g_gi + (size_t)bk*768;
    const float* gh = g_gh + (size_t)bk*768;
    float sl = g_slots[bk*256 + t];
    float r  = 1.f / (1.f + __expf(-(gi[t]       + gh[t])));
    float z  = 1.f / (1.f + __expf(-(gi[256 + t] + gh[256 + t])));
    float nn = tanhf(gi[512 + t] + r * gh[512 + t]);
    float h  = (1.f - z) * nn + z * sl;

    __shared__ float hn[256], ms[256];
    __shared__ float r1[8], r2[8];
    __shared__ float smv[2];
    float s = h, s2 = h*h;
    for (int o = 16; o; o >>= 1) { s += __shfl_down_sync(0xffffffffu, s, o); s2 += __shfl_down_sync(0xffffffffu, s2, o); }
    if ((t & 31) == 0) { r1[t>>5] = s; r2[t>>5] = s2; }
    __syncthreads();
    if (t == 0) {
        float ts = 0.f, ts2 = 0.f;
        #pragma unroll
        for (int w = 0; w < 8; w++) { ts += r1[w]; ts2 += r2[w]; }
        float m = ts * (1.f/256.f);
        float var = ts2 * (1.f/256.f) - m*m;
        smv[0] = m; smv[1] = rsqrtf(var + 1e-5f);
    }
    __syncthreads();
    hn[t] = (h - smv[0]) * smv[1] * gm[t] + bm[t];
    __syncthreads();
    float acc = b1[t];
    #pragma unroll 4
    for (int d = 0; d < 256; d++) acc += hn[d] * g_W1T[d*256 + t];
    ms[t] = fmaxf(acc, 0.f);
    __syncthreads();
    float o = h + b2[t];
    #pragma unroll 4
    for (int j = 0; j < 256; j++) o += ms[j] * g_W2T[j*256 + t];
    g_slots[bk*256 + t] = o;

    // ---- fused slot_q tail: zero U/S, q = LN(new slots) @ Wq^T ----
    g_U[bk*256 + t] = 0.f;
    if (t == 0) g_S[bk] = 0.f;
    __syncthreads();
    s = o; s2 = o*o;
    for (int off = 16; off; off >>= 1) { s += __shfl_down_sync(0xffffffffu, s, off); s2 += __shfl_down_sync(0xffffffffu, s2, off); }
    if ((t & 31) == 0) { r1[t>>5] = s; r2[t>>5] = s2; }
    __syncthreads();
    if (t == 0) {
        float ts = 0.f, ts2 = 0.f;
        #pragma unroll
        for (int w = 0; w < 8; w++) { ts += r1[w]; ts2 += r2[w]; }
        float m = ts * (1.f/256.f);
        float var = ts2 * (1.f/256.f) - m*m;
        smv[0] = m; smv[1] = rsqrtf(var + 1e-5f);
    }
    __syncthreads();
    hn[t] = (o - smv[0]) * smv[1] * gs[t] + bs[t];
    __syncthreads();
    float qa = 0.f;
    #pragma unroll 4
    for (int d = 0; d < 256; d++) qa += hn[d] * g_WqT[d*256 + t];
    g_q[bk*256 + t] = qa;
}

// ---------------- final confidence blend ----------------
__global__ void __launch_bounds__(256) finalize(const float* __restrict__ prev, float* __restrict__ out_slots) {
    int bk = blockIdx.x;
    int t = threadIdx.x;
    float mean = g_S[bk] * (1.f / 4096.f);
    float mask = 1.f / (1.f + __expf(-mean));
    out_slots[bk*256 + t] = g_slots[bk*256 + t] * mask + prev[bk*256 + t] * (1.f - mask);
}

// ---------------- launch ----------------
extern "C" void kernel_launch(void* const* d_in, const int* in_sizes, int n_in,
                              void* d_out, int out_size) {
    const float* features = (const float*)d_in[0];
    const float* prev     = (const float*)d_in[1];
    const float* gin      = (const float*)d_in[2];
    const float* bin      = (const float*)d_in[3];
    const float* gs       = (const float*)d_in[4];
    const float* bs       = (const float*)d_in[5];
    const float* gm       = (const float*)d_in[6];
    const float* bm       = (const float*)d_in[7];
    const float* Wq       = (const float*)d_in[8];
    const float* Wk       = (const float*)d_in[9];
    const float* Wv       = (const float*)d_in[10];
    const float* Wih      = (const float*)d_in[11];
    const float* Whh      = (const float*)d_in[12];
    const float* bih      = (const float*)d_in[13];
    const float* bhh      = (const float*)d_in[14];
    const float* W1       = (const float*)d_in[15];
    const float* b1       = (const float*)d_in[16];
    const float* W2       = (const float*)d_in[17];
    const float* b2       = (const float*)d_in[18];

    float* out_slots = (float*)d_out;
    float* out_attn  = out_slots + BB*KSLOT*DS;

    cudaFuncSetAttribute((const void*)attn_pass<false>, cudaFuncAttributeMaxDynamicSharedMemorySize, ATTN_SMEM_B);
    cudaFuncSetAttribute((const void*)attn_pass<true>,  cudaFuncAttributeMaxDynamicSharedMemorySize, ATTN_SMEM_B);
    cudaFuncSetAttribute((const void*)gemm_mma, cudaFuncAttributeMaxDynamicSharedMemorySize, GEMM_SMEM);

    // launch 1: all prep
    prep_all<<<1536, 256>>>(Wk, Wv, gin, bin, Wq, Wih, Whh, W1, W2, prev, gs, bs);
    // launch 2: LN stats + fp16 cast
    row_stats_split<<<NROWS/8, 256>>>(features);
    // launch 3: projection GEMM (R10 config)
    gemm_mma<<<dim3(4, NROWS/128), 256, GEMM_SMEM>>>();

    // launch 4 (PROFILED): first attention sweep
    for (int it = 0; it < 3; it++) {
        attn_pass<false><<<dim3(BB, CHUNKS), 256, ATTN_SMEM_B>>>(nullptr);
        gru_gemm<<<BB*24, 256>>>(bih, bhh);
        gru_mlp<<<BB*KSLOT, 256>>>(gm, bm, b1, b2, gs, bs);
    }

    attn_pass<true><<<dim3(BB, CHUNKS), 256, ATTN_SMEM_B>>>(out_attn);
    finalize<<<BB*KSLOT, 256>>>(prev, out_slots);

    (void)in_sizes; (void)n_in; (void)out_size;
}